// round 6
// baseline (speedup 1.0000x reference)
#include <cuda_runtime.h>
#include <math.h>

#define N_ATOMS 512
#define NQC     8
#define NT      16      // targets per block
#define NS      16      // sources per chunk
#define NCH     32      // source chunks
#define TPB     128     // NT * NQC
#define NTQ     (N_ATOMS * NQC)   // 4096
#define NTB     (N_ATOMS / NT)    // 32 target blocks

// compact accumulators: [18][tq] (288 KB, L2-resident). Zero at start; the
// fused finalize re-zeroes after consuming, so every replay sees clean state.
__device__ float        g_acc[18 * NTQ];
__device__ unsigned int g_cnt[NTB];   // per-target-block completion counters
__device__ unsigned int g_fin;        // finalizer counter
__device__ float        g_pot;        // pot accumulator

__global__ __launch_bounds__(TPB, 8)
void pairs_kernel(const float* __restrict__ gq, const float* __restrict__ gr,
                  const float* __restrict__ gu, const float* __restrict__ gQ,
                  const float* __restrict__ gkap, const float* __restrict__ gal,
                  float* __restrict__ out)
{
    __shared__ __align__(16) float s_sr[NS * 3];
    __shared__ __align__(16) float s_tr[NT * 3];
    __shared__ __align__(16) float s_q [NS * NQC];          // 512 B
    __shared__ __align__(16) float s_u [NS * NQC * 4];      // 2 KB (stride-4 pad)
    __shared__ __align__(16) float s_S [NS * NQC * 8];      // 4 KB {S00,S01,S02,S11,S12,S22,trq,0}
    __shared__ __align__(16) float s_pair[NS * NT * 8];     // 8 KB {g,c1,c2,c3,c4,dx,dy,dz}
    __shared__ unsigned int s_last;
    __shared__ float s_red[4];

    const int tid = threadIdx.x;
    const int t0  = blockIdx.x * NT;
    const int s0  = blockIdx.y * NS;

    // ---- phase 1: stage source + target data into smem ----
    for (int i = tid; i < NS * 3; i += TPB) s_sr[i] = gr[s0 * 3 + i];
    for (int i = tid; i < NT * 3; i += TPB) s_tr[i] = gr[t0 * 3 + i];
    {
        const float4* src = (const float4*)(gq + s0 * NQC);
        float4* dst = (float4*)s_q;
        for (int i = tid; i < NS * NQC / 4; i += TPB) dst[i] = src[i];
    }
    for (int i = tid; i < NS * NQC; i += TPB) {
        const float* up = gu + (s0 * NQC + i) * 3;
        s_u[i * 4 + 0] = up[0]; s_u[i * 4 + 1] = up[1]; s_u[i * 4 + 2] = up[2];
    }
    for (int i = tid; i < NS * NQC; i += TPB) {
        const float* Qp = gQ + (s0 * NQC + i) * 9;
        const float q00 = Qp[0], q01 = Qp[1], q02 = Qp[2];
        const float q10 = Qp[3], q11 = Qp[4], q12 = Qp[5];
        const float q20 = Qp[6], q21 = Qp[7], q22 = Qp[8];
        float* d = &s_S[i * 8];
        d[0] = q00 + q00; d[1] = q01 + q10; d[2] = q02 + q20;
        d[3] = q11 + q11; d[4] = q12 + q21; d[5] = q22 + q22;
        d[6] = q00 + q11 + q22; d[7] = 0.f;
    }
    __syncthreads();

    // ---- phase 2: pair scalar kernels (g, D1..D4)*nc and displacement ----
    const float A_ERF = 0.70710678118654752f;                         // 1/sqrt(2)
    const float NCE = (float)(90.4756 / (2.0 * 3.14159265358979323846));
    const float NCG = (float)((90.4756 / (2.0 * 3.14159265358979323846))
                              * 0.79788456080286536);                 // nc * 2a/sqrt(pi)

#pragma unroll
    for (int p = tid; p < NS * NT; p += TPB) {
        const int s  = p >> 4;
        const int tl = p & 15;
        float dx = s_tr[tl * 3 + 0] - s_sr[s * 3 + 0];
        float dy = s_tr[tl * 3 + 1] - s_sr[s * 3 + 1];
        float dz = s_tr[tl * 3 + 2] - s_sr[s * 3 + 2];
        float g = 0.f, c1 = 0.f, c2 = 0.f, c3 = 0.f, c4 = 0.f;
        if (t0 + tl != s0 + s) {
            float r2 = dx * dx + dy * dy + dz * dz;
            float rr = sqrtf(r2);
            float E  = NCE * erff(A_ERF * rr);
            float G  = NCG * expf(-0.5f * rr * rr);
            float ir = 1.0f / rr;
            float ir2 = ir * ir,  ir3 = ir2 * ir,  ir4 = ir2 * ir2, ir5 = ir4 * ir;
            float ir6 = ir4 * ir2, ir7 = ir6 * ir, ir8 = ir4 * ir4, ir9 = ir8 * ir;
            g  = E * ir;
            c1 = G * ir2 - E * ir3;
            c2 = 3.0f * E * ir5 - 3.0f * G * ir4 - G * ir2;                       // 2*a2 = 1
            c3 = -15.0f * E * ir7 + 15.0f * G * ir6 + 5.0f * G * ir4 + G * ir2;   // 10*a2=5, 4*a2^2=1
            c4 = 105.0f * E * ir9 - 105.0f * G * ir8 - 35.0f * G * ir6
                 - 7.0f * G * ir4 - G * ir2;                                      // 70a2=35, 28a2^2=7, 8a2^3=1
        }
        float4* op = (float4*)&s_pair[p * 8];
        op[0] = make_float4(g, c1, c2, c3);
        op[1] = make_float4(c4, dx, dy, dz);
    }
    __syncthreads();

    // ---- phase 3: per-(target, channel) accumulation over the source tile ----
    const int tl = tid >> 3;
    const int qc = tid & 7;

    float A0 = 0.f, A1 = 0.f, A2 = 0.f;
    float Eux = 0.f, Euy = 0.f, Euz = 0.f;
    float EQx = 0.f, EQy = 0.f, EQz = 0.f;
    float Efx = 0.f, Efy = 0.f, Efz = 0.f;
    float Qxx = 0.f, Qxy = 0.f, Qxz = 0.f, Qyy = 0.f, Qyz = 0.f, Qzz = 0.f;

#pragma unroll 4
    for (int s = 0; s < NS; s++) {
        const float4 pa = *(const float4*)&s_pair[(s * NT + tl) * 8];
        const float4 pb = *(const float4*)&s_pair[(s * NT + tl) * 8 + 4];
        const float g  = pa.x, c1 = pa.y, c2 = pa.z, c3 = pa.w;
        const float c4 = pb.x, dx = pb.y, dy = pb.z, dz = pb.w;
        const float qs = s_q[s * NQC + qc];
        const float4 uv = *(const float4*)&s_u[(s * NQC + qc) * 4];
        const float ux = uv.x, uy = uv.y, uz = uv.z;
        const float4 sa = *(const float4*)&s_S[(s * NQC + qc) * 8];
        const float4 sb = *(const float4*)&s_S[(s * NQC + qc) * 8 + 4];
        const float S00 = sa.x, S01 = sa.y, S02 = sa.z, S11 = sa.w;
        const float S12 = sb.x, S22 = sb.y, trq = sb.z;

        const float ud  = fmaf(ux, dx, fmaf(uy, dy, uz * dz));
        // s = S·d  (== Q·d + Qᵀ·d);  dQd = ½ dᵀS d
        const float sx = fmaf(S00, dx, fmaf(S01, dy, S02 * dz));
        const float sy = fmaf(S01, dx, fmaf(S11, dy, S12 * dz));
        const float sz = fmaf(S02, dx, fmaf(S12, dy, S22 * dz));
        const float dQd = 0.5f * fmaf(dx, sx, fmaf(dy, sy, dz * sz));

        // potentials at target
        A0 = fmaf(g, qs, A0);
        A1 = fmaf(-c1, ud, A1);
        A2 = fmaf(0.5f * c2, dQd, A2);
        A2 = fmaf(0.5f * c1, trq, A2);

        // E_u (dipole field)
        const float t2u = c2 * ud;
        Eux = fmaf(t2u, dx, fmaf(c1, ux, Eux));
        Euy = fmaf(t2u, dy, fmaf(c1, uy, Euy));
        Euz = fmaf(t2u, dz, fmaf(c1, uz, Euz));

        // E_Q (quadrupole field)
        const float Aq = -0.5f * fmaf(c3, dQd, c2 * trq);
        const float Bq = -0.5f * c2;
        EQx = fmaf(Aq, dx, fmaf(Bq, sx, EQx));
        EQy = fmaf(Aq, dy, fmaf(Bq, sy, EQy));
        EQz = fmaf(Aq, dz, fmaf(Bq, sz, EQz));

        // field from charges
        const float t1q = c1 * qs;
        Efx = fmaf(-t1q, dx, Efx);
        Efy = fmaf(-t1q, dy, Efy);
        Efz = fmaf(-t1q, dz, Efz);

        // QQ (symmetric 3x3)
        const float cA = fmaf(c4, dQd, c3 * trq);
        const float cD = fmaf(c3, dQd, c2 * trq);
        const float hx = c3 * sx, hy = c3 * sy, hz = c3 * sz;
        Qxx = fmaf(cA, dx * dx, Qxx);
        Qxx = fmaf(hx + hx, dx, Qxx);
        Qxx = fmaf(c2, S00, Qxx + cD);
        Qyy = fmaf(cA, dy * dy, Qyy);
        Qyy = fmaf(hy + hy, dy, Qyy);
        Qyy = fmaf(c2, S11, Qyy + cD);
        Qzz = fmaf(cA, dz * dz, Qzz);
        Qzz = fmaf(hz + hz, dz, Qzz);
        Qzz = fmaf(c2, S22, Qzz + cD);
        Qxy = fmaf(cA, dx * dy, Qxy);
        Qxy = fmaf(hx, dy, Qxy);
        Qxy = fmaf(hy, dx, Qxy);
        Qxy = fmaf(c2, S01, Qxy);
        Qxz = fmaf(cA, dx * dz, Qxz);
        Qxz = fmaf(hx, dz, Qxz);
        Qxz = fmaf(hz, dx, Qxz);
        Qxz = fmaf(c2, S02, Qxz);
        Qyz = fmaf(cA, dy * dz, Qyz);
        Qyz = fmaf(hy, dz, Qyz);
        Qyz = fmaf(hz, dy, Qyz);
        Qyz = fmaf(c2, S12, Qyz);
    }

    // ---- accumulate partials into compact L2-resident array ----
    {
        const int tqi = (t0 + tl) * NQC + qc;
        const float acc[18] = {A0, A1, A2, Eux, Euy, Euz, EQx, EQy, EQz,
                               Efx, Efy, Efz, Qxx, Qxy, Qxz, Qyy, Qyz, Qzz};
#pragma unroll
        for (int k = 0; k < 18; k++)
            atomicAdd(&g_acc[k * NTQ + tqi], acc[k]);
    }

    // ---- fused finalize: last chunk-CTA per target block finalizes it ----
    __threadfence();
    __syncthreads();
    if (tid == 0) s_last = atomicAdd(&g_cnt[blockIdx.x], 1u);
    __syncthreads();
    if (s_last == NCH - 1) {
        const int tqi = blockIdx.x * TPB + tid;   // NT*NQC == TPB

        float acc[18];
#pragma unroll
        for (int k = 0; k < 18; k++)
            acc[k] = __ldcg(&g_acc[k * NTQ + tqi]);
#pragma unroll
        for (int k = 0; k < 18; k++)
            g_acc[k * NTQ + tqi] = 0.0f;          // self-clean for next replay

        const float fA0 = acc[0], fA1 = acc[1], fA2 = acc[2];
        const float fEux = acc[3], fEuy = acc[4], fEuz = acc[5];
        const float fEQx = acc[6], fEQy = acc[7], fEQz = acc[8];
        const float fEfx = acc[9], fEfy = acc[10], fEfz = acc[11];
        const float fQxx = acc[12], fQxy = acc[13], fQxz = acc[14];
        const float fQyy = acc[15], fQyz = acc[16], fQzz = acc[17];

        const float qv  = gq[tqi];
        const float kap = gkap[tqi];
        const float al  = gal[tqi];
        const float ux = gu[tqi * 3 + 0], uy = gu[tqi * 3 + 1], uz = gu[tqi * 3 + 2];
        const float* Qp = gQ + tqi * 9;

        const float ephi = fA0 + fA1 + fA2;
        out[1 + tqi] = -kap * ephi;                               // q_induced

        const float ex = fEfx + fEux + fEQx;
        const float ey = fEfy + fEuy + fEQy;
        const float ez = fEfz + fEuz + fEQz;
        out[1 + NTQ + tqi * 3 + 0] = al * ex;                     // u_induced
        out[1 + NTQ + tqi * 3 + 1] = al * ey;
        out[1 + NTQ + tqi * 3 + 2] = al * ez;

        const float qQQ = Qp[0] * fQxx + Qp[4] * fQyy + Qp[8] * fQzz
                        + (Qp[1] + Qp[3]) * fQxy + (Qp[2] + Qp[6]) * fQxz
                        + (Qp[5] + Qp[7]) * fQyz;
        const float uEu = ux * fEux + uy * fEuy + uz * fEuz;
        const float uEQ = ux * fEQx + uy * fEQy + uz * fEQz;
        const float e2  = ex * ex + ey * ey + ez * ez;

        float pot = 0.5f * fA0 * qv + fA1 * qv - 0.5f * uEu + qv * fA2
                  + 0.125f * qQQ - uEQ
                  - 0.5f * kap * ephi * ephi
                  - 0.5f * al * e2;

#pragma unroll
        for (int off = 16; off > 0; off >>= 1)
            pot += __shfl_xor_sync(0xFFFFFFFFu, pot, off);
        if ((tid & 31) == 0) s_red[tid >> 5] = pot;
        __syncthreads();
        if (tid == 0) {
            const float bp = s_red[0] + s_red[1] + s_red[2] + s_red[3];
            atomicAdd(&g_pot, bp);
            __threadfence();
            const unsigned int of = atomicAdd(&g_fin, 1u);
            if (of == NTB - 1) {                  // globally last finalizer
                const float tot = atomicAdd(&g_pot, 0.0f);  // coherent read
                out[0] = tot;
                g_pot = 0.0f;                     // self-clean
                g_fin = 0u;
            }
            g_cnt[blockIdx.x] = 0u;               // self-clean
        }
    }
}

extern "C" void kernel_launch(void* const* d_in, const int* in_sizes, int n_in,
                              void* d_out, int out_size)
{
    (void)in_sizes; (void)n_in; (void)out_size;
    const float* q     = (const float*)d_in[0];
    const float* r     = (const float*)d_in[1];
    // d_in[2] = cell (zero -> realspace branch), d_in[3] = batch (single graph): unused
    const float* u     = (const float*)d_in[4];
    const float* quad  = (const float*)d_in[5];
    const float* kappa = (const float*)d_in[6];
    const float* alpha = (const float*)d_in[7];
    float* out = (float*)d_out;

    pairs_kernel<<<dim3(NTB, NCH), TPB>>>(q, r, u, quad, kappa, alpha, out);
}

// round 7
// speedup vs baseline: 1.1191x; 1.1191x over previous
#include <cuda_runtime.h>
#include <math.h>

#define N_ATOMS 512
#define NQC     8
#define NT      16      // targets per block
#define NS      16      // sources per chunk
#define NCH     32      // source chunks
#define TPB     128     // NT * NQC
#define NTQ     (N_ATOMS * NQC)   // 4096
#define NTB     (N_ATOMS / NT)    // 32 target blocks

// compact accumulators: [18][tq] (288 KB, L2-resident). Zero at process start;
// finalize re-zeroes after consuming, so every replay sees clean state.
__device__ float g_acc[18 * NTQ];

__global__ __launch_bounds__(TPB, 8)
void pairs_kernel(const float* __restrict__ gq, const float* __restrict__ gr,
                  const float* __restrict__ gu, const float* __restrict__ gQ,
                  float* __restrict__ out)
{
    __shared__ __align__(16) float s_sr[NS * 3];
    __shared__ __align__(16) float s_tr[NT * 3];
    __shared__ __align__(16) float s_q [NS * NQC];          // 512 B
    __shared__ __align__(16) float s_u [NS * NQC * 4];      // 2 KB (stride-4 pad)
    __shared__ __align__(16) float s_S [NS * NQC * 8];      // 4 KB {S00,S01,S02,S11,S12,S22,trq,0}
    __shared__ __align__(16) float s_pair[NS * NT * 8];     // 8 KB {g,c1,c2,c3,c4,dx,dy,dz}

    const int tid = threadIdx.x;
    const int t0  = blockIdx.x * NT;
    const int s0  = blockIdx.y * NS;

    if (blockIdx.x == 0 && blockIdx.y == 0 && tid == 0)
        out[0] = 0.0f;   // pot accumulator, consumed by finalize after this grid completes

    // ---- phase 1: stage source + target data into smem ----
    for (int i = tid; i < NS * 3; i += TPB) s_sr[i] = gr[s0 * 3 + i];
    for (int i = tid; i < NT * 3; i += TPB) s_tr[i] = gr[t0 * 3 + i];
    {
        const float4* src = (const float4*)(gq + s0 * NQC);
        float4* dst = (float4*)s_q;
        for (int i = tid; i < NS * NQC / 4; i += TPB) dst[i] = src[i];
    }
    for (int i = tid; i < NS * NQC; i += TPB) {
        const float* up = gu + (s0 * NQC + i) * 3;
        s_u[i * 4 + 0] = up[0]; s_u[i * 4 + 1] = up[1]; s_u[i * 4 + 2] = up[2];
    }
    for (int i = tid; i < NS * NQC; i += TPB) {
        const float* Qp = gQ + (s0 * NQC + i) * 9;
        const float q00 = Qp[0], q01 = Qp[1], q02 = Qp[2];
        const float q10 = Qp[3], q11 = Qp[4], q12 = Qp[5];
        const float q20 = Qp[6], q21 = Qp[7], q22 = Qp[8];
        float* d = &s_S[i * 8];
        d[0] = q00 + q00; d[1] = q01 + q10; d[2] = q02 + q20;
        d[3] = q11 + q11; d[4] = q12 + q21; d[5] = q22 + q22;
        d[6] = q00 + q11 + q22; d[7] = 0.f;
    }
    __syncthreads();

    // ---- phase 2: pair scalar kernels (g, D1..D4)*nc and displacement ----
    const float A_ERF = 0.70710678118654752f;                         // 1/sqrt(2)
    const float NCE = (float)(90.4756 / (2.0 * 3.14159265358979323846));
    const float NCG = (float)((90.4756 / (2.0 * 3.14159265358979323846))
                              * 0.79788456080286536);                 // nc * 2a/sqrt(pi)

#pragma unroll
    for (int p = tid; p < NS * NT; p += TPB) {
        const int s  = p >> 4;
        const int tl = p & 15;
        float dx = s_tr[tl * 3 + 0] - s_sr[s * 3 + 0];
        float dy = s_tr[tl * 3 + 1] - s_sr[s * 3 + 1];
        float dz = s_tr[tl * 3 + 2] - s_sr[s * 3 + 2];
        float g = 0.f, c1 = 0.f, c2 = 0.f, c3 = 0.f, c4 = 0.f;
        if (t0 + tl != s0 + s) {
            float r2 = dx * dx + dy * dy + dz * dz;
            float rr = sqrtf(r2);
            float E  = NCE * erff(A_ERF * rr);
            float G  = NCG * expf(-0.5f * rr * rr);
            float ir = 1.0f / rr;
            float ir2 = ir * ir,  ir3 = ir2 * ir,  ir4 = ir2 * ir2, ir5 = ir4 * ir;
            float ir6 = ir4 * ir2, ir7 = ir6 * ir, ir8 = ir4 * ir4, ir9 = ir8 * ir;
            g  = E * ir;
            c1 = G * ir2 - E * ir3;
            c2 = 3.0f * E * ir5 - 3.0f * G * ir4 - G * ir2;                       // 2*a2 = 1
            c3 = -15.0f * E * ir7 + 15.0f * G * ir6 + 5.0f * G * ir4 + G * ir2;   // 10*a2=5, 4*a2^2=1
            c4 = 105.0f * E * ir9 - 105.0f * G * ir8 - 35.0f * G * ir6
                 - 7.0f * G * ir4 - G * ir2;                                      // 70a2=35, 28a2^2=7, 8a2^3=1
        }
        float4* op = (float4*)&s_pair[p * 8];
        op[0] = make_float4(g, c1, c2, c3);
        op[1] = make_float4(c4, dx, dy, dz);
    }
    __syncthreads();

    // ---- phase 3: per-(target, channel) accumulation over the source tile ----
    const int tl = tid >> 3;
    const int qc = tid & 7;

    float A0 = 0.f, A1 = 0.f, A2 = 0.f;
    float Eux = 0.f, Euy = 0.f, Euz = 0.f;
    float EQx = 0.f, EQy = 0.f, EQz = 0.f;
    float Efx = 0.f, Efy = 0.f, Efz = 0.f;
    float Qxx = 0.f, Qxy = 0.f, Qxz = 0.f, Qyy = 0.f, Qyz = 0.f, Qzz = 0.f;

#pragma unroll 4
    for (int s = 0; s < NS; s++) {
        const float4 pa = *(const float4*)&s_pair[(s * NT + tl) * 8];
        const float4 pb = *(const float4*)&s_pair[(s * NT + tl) * 8 + 4];
        const float g  = pa.x, c1 = pa.y, c2 = pa.z, c3 = pa.w;
        const float c4 = pb.x, dx = pb.y, dy = pb.z, dz = pb.w;
        const float qs = s_q[s * NQC + qc];
        const float4 uv = *(const float4*)&s_u[(s * NQC + qc) * 4];
        const float ux = uv.x, uy = uv.y, uz = uv.z;
        const float4 sa = *(const float4*)&s_S[(s * NQC + qc) * 8];
        const float4 sb = *(const float4*)&s_S[(s * NQC + qc) * 8 + 4];
        const float S00 = sa.x, S01 = sa.y, S02 = sa.z, S11 = sa.w;
        const float S12 = sb.x, S22 = sb.y, trq = sb.z;

        const float ud  = fmaf(ux, dx, fmaf(uy, dy, uz * dz));
        // s = S·d  (== Q·d + Qᵀ·d);  dQd = ½ dᵀS d
        const float sx = fmaf(S00, dx, fmaf(S01, dy, S02 * dz));
        const float sy = fmaf(S01, dx, fmaf(S11, dy, S12 * dz));
        const float sz = fmaf(S02, dx, fmaf(S12, dy, S22 * dz));
        const float dQd = 0.5f * fmaf(dx, sx, fmaf(dy, sy, dz * sz));

        // potentials at target
        A0 = fmaf(g, qs, A0);
        A1 = fmaf(-c1, ud, A1);
        A2 = fmaf(0.5f * c2, dQd, A2);
        A2 = fmaf(0.5f * c1, trq, A2);

        // E_u (dipole field)
        const float t2u = c2 * ud;
        Eux = fmaf(t2u, dx, fmaf(c1, ux, Eux));
        Euy = fmaf(t2u, dy, fmaf(c1, uy, Euy));
        Euz = fmaf(t2u, dz, fmaf(c1, uz, Euz));

        // E_Q (quadrupole field)
        const float Aq = -0.5f * fmaf(c3, dQd, c2 * trq);
        const float Bq = -0.5f * c2;
        EQx = fmaf(Aq, dx, fmaf(Bq, sx, EQx));
        EQy = fmaf(Aq, dy, fmaf(Bq, sy, EQy));
        EQz = fmaf(Aq, dz, fmaf(Bq, sz, EQz));

        // field from charges
        const float t1q = c1 * qs;
        Efx = fmaf(-t1q, dx, Efx);
        Efy = fmaf(-t1q, dy, Efy);
        Efz = fmaf(-t1q, dz, Efz);

        // QQ (symmetric 3x3)
        const float cA = fmaf(c4, dQd, c3 * trq);
        const float cD = fmaf(c3, dQd, c2 * trq);
        const float hx = c3 * sx, hy = c3 * sy, hz = c3 * sz;
        Qxx = fmaf(cA, dx * dx, Qxx);
        Qxx = fmaf(hx + hx, dx, Qxx);
        Qxx = fmaf(c2, S00, Qxx + cD);
        Qyy = fmaf(cA, dy * dy, Qyy);
        Qyy = fmaf(hy + hy, dy, Qyy);
        Qyy = fmaf(c2, S11, Qyy + cD);
        Qzz = fmaf(cA, dz * dz, Qzz);
        Qzz = fmaf(hz + hz, dz, Qzz);
        Qzz = fmaf(c2, S22, Qzz + cD);
        Qxy = fmaf(cA, dx * dy, Qxy);
        Qxy = fmaf(hx, dy, Qxy);
        Qxy = fmaf(hy, dx, Qxy);
        Qxy = fmaf(c2, S01, Qxy);
        Qxz = fmaf(cA, dx * dz, Qxz);
        Qxz = fmaf(hx, dz, Qxz);
        Qxz = fmaf(hz, dx, Qxz);
        Qxz = fmaf(c2, S02, Qxz);
        Qyz = fmaf(cA, dy * dz, Qyz);
        Qyz = fmaf(hy, dz, Qyz);
        Qyz = fmaf(hz, dy, Qyz);
        Qyz = fmaf(c2, S12, Qyz);
    }

    // ---- accumulate partials into compact L2-resident array (red ops) ----
    const int tqi = (t0 + tl) * NQC + qc;
    const float acc[18] = {A0, A1, A2, Eux, Euy, Euz, EQx, EQy, EQz,
                           Efx, Efy, Efz, Qxx, Qxy, Qxz, Qyy, Qyz, Qzz};
#pragma unroll
    for (int k = 0; k < 18; k++)
        atomicAdd(&g_acc[k * NTQ + tqi], acc[k]);
}

// PDL secondary: starts while pairs drains, prefetches inputs that pairs does
// not write, then grid-syncs before touching g_acc / out.
__global__ __launch_bounds__(32)
void finalize_kernel(const float* __restrict__ gq, const float* __restrict__ gu,
                     const float* __restrict__ gQ, const float* __restrict__ gkap,
                     const float* __restrict__ gal, float* __restrict__ out)
{
    const int tqi = blockIdx.x * 32 + threadIdx.x;

    // prefetch inputs independent of pairs' outputs
    const float qv  = gq[tqi];
    const float kap = gkap[tqi];
    const float al  = gal[tqi];
    const float ux = gu[tqi * 3 + 0], uy = gu[tqi * 3 + 1], uz = gu[tqi * 3 + 2];
    float Qpv[9];
#pragma unroll
    for (int k = 0; k < 9; k++) Qpv[k] = gQ[tqi * 9 + k];

    // wait for pairs_kernel completion (all its atomics + out[0]=0 visible)
    cudaGridDependencySynchronize();

    float acc[18];
#pragma unroll
    for (int k = 0; k < 18; k++)
        acc[k] = g_acc[k * NTQ + tqi];
    // re-zero for the next invocation (self-cleaning accumulator)
#pragma unroll
    for (int k = 0; k < 18; k++)
        g_acc[k * NTQ + tqi] = 0.0f;

    const float A0 = acc[0], A1 = acc[1], A2 = acc[2];
    const float Eux = acc[3], Euy = acc[4], Euz = acc[5];
    const float EQx = acc[6], EQy = acc[7], EQz = acc[8];
    const float Efx = acc[9], Efy = acc[10], Efz = acc[11];
    const float Qxx = acc[12], Qxy = acc[13], Qxz = acc[14];
    const float Qyy = acc[15], Qyz = acc[16], Qzz = acc[17];

    const float ephi = A0 + A1 + A2;
    out[1 + tqi] = -kap * ephi;                               // q_induced

    const float ex = Efx + Eux + EQx;
    const float ey = Efy + Euy + EQy;
    const float ez = Efz + Euz + EQz;
    out[1 + NTQ + tqi * 3 + 0] = al * ex;                     // u_induced
    out[1 + NTQ + tqi * 3 + 1] = al * ey;
    out[1 + NTQ + tqi * 3 + 2] = al * ez;

    const float qQQ = Qpv[0] * Qxx + Qpv[4] * Qyy + Qpv[8] * Qzz
                    + (Qpv[1] + Qpv[3]) * Qxy + (Qpv[2] + Qpv[6]) * Qxz
                    + (Qpv[5] + Qpv[7]) * Qyz;
    const float uEu = ux * Eux + uy * Euy + uz * Euz;
    const float uEQ = ux * EQx + uy * EQy + uz * EQz;
    const float e2  = ex * ex + ey * ey + ez * ez;

    float pot = 0.5f * A0 * qv + A1 * qv - 0.5f * uEu + qv * A2
              + 0.125f * qQQ - uEQ
              - 0.5f * kap * ephi * ephi
              - 0.5f * al * e2;

    // warp-shuffle reduction, one atomic per block
#pragma unroll
    for (int off = 16; off > 0; off >>= 1)
        pot += __shfl_xor_sync(0xFFFFFFFFu, pot, off);
    if (threadIdx.x == 0) atomicAdd(&out[0], pot);
}

extern "C" void kernel_launch(void* const* d_in, const int* in_sizes, int n_in,
                              void* d_out, int out_size)
{
    (void)in_sizes; (void)n_in; (void)out_size;
    const float* q     = (const float*)d_in[0];
    const float* r     = (const float*)d_in[1];
    // d_in[2] = cell (zero -> realspace branch), d_in[3] = batch (single graph): unused
    const float* u     = (const float*)d_in[4];
    const float* quad  = (const float*)d_in[5];
    const float* kappa = (const float*)d_in[6];
    const float* alpha = (const float*)d_in[7];
    float* out = (float*)d_out;

    pairs_kernel<<<dim3(NTB, NCH), TPB>>>(q, r, u, quad, out);

    // finalize with Programmatic Dependent Launch: overlaps launch + input
    // prefetch with pairs' tail; cudaGridDependencySynchronize() inside the
    // kernel provides the ordering on g_acc / out.
    cudaLaunchConfig_t cfg = {};
    cfg.gridDim  = dim3(NTQ / 32, 1, 1);
    cfg.blockDim = dim3(32, 1, 1);
    cfg.dynamicSmemBytes = 0;
    cfg.stream = 0;
    cudaLaunchAttribute attrs[1];
    attrs[0].id = cudaLaunchAttributeProgrammaticStreamSerialization;
    attrs[0].val.programmaticStreamSerializationAllowed = 1;
    cfg.attrs = attrs;
    cfg.numAttrs = 1;
    cudaLaunchKernelEx(&cfg, finalize_kernel, q, u, quad, kappa, alpha, out);
}

// round 8
// speedup vs baseline: 1.1863x; 1.0600x over previous
#include <cuda_runtime.h>
#include <math.h>

#define N_ATOMS 512
#define NQC     8
#define NT      16      // targets per block
#define NS      16      // sources per chunk
#define NCH     32      // source chunks
#define TPB     128     // NT * NQC
#define NTQ     (N_ATOMS * NQC)   // 4096
#define NTB     (N_ATOMS / NT)    // 32 target blocks

// compact accumulators: [18][tq] (288 KB, L2-resident). Zero at process start;
// finalize re-zeroes after consuming, so every replay sees clean state.
__device__ float g_acc[18 * NTQ];

__global__ __launch_bounds__(TPB, 8)
void pairs_kernel(const float* __restrict__ gq, const float* __restrict__ gr,
                  const float* __restrict__ gu, const float* __restrict__ gQ,
                  float* __restrict__ out)
{
    __shared__ __align__(16) float s_sr[NS * 3];
    __shared__ __align__(16) float s_tr[NT * 3];
    // packed source-channel data, stride 12: {q,ux,uy,uz | S00,S01,S02,S11 | S12,S22,trq,0}
    __shared__ __align__(16) float s_src[NS * NQC * 12];    // 6 KB
    __shared__ __align__(16) float s_pair[NS * NT * 8];     // 8 KB {g,c1,c2,c3,c4,dx,dy,dz}

    const int tid = threadIdx.x;
    const int t0  = blockIdx.x * NT;
    const int s0  = blockIdx.y * NS;

    if (blockIdx.x == 0 && blockIdx.y == 0 && tid == 0)
        out[0] = 0.0f;   // pot accumulator, consumed by finalize after this grid completes

    // ---- phase 1: stage source + target data into smem ----
    for (int i = tid; i < NS * 3; i += TPB) s_sr[i] = gr[s0 * 3 + i];
    for (int i = tid; i < NT * 3; i += TPB) s_tr[i] = gr[t0 * 3 + i];
    for (int i = tid; i < NS * NQC; i += TPB) {
        const float qv = gq[s0 * NQC + i];
        const float* up = gu + (s0 * NQC + i) * 3;
        const float* Qp = gQ + (s0 * NQC + i) * 9;
        const float q00 = Qp[0], q01 = Qp[1], q02 = Qp[2];
        const float q10 = Qp[3], q11 = Qp[4], q12 = Qp[5];
        const float q20 = Qp[6], q21 = Qp[7], q22 = Qp[8];
        float4* d = (float4*)&s_src[i * 12];
        d[0] = make_float4(qv, up[0], up[1], up[2]);
        d[1] = make_float4(q00 + q00, q01 + q10, q02 + q20, q11 + q11);
        d[2] = make_float4(q12 + q21, q22 + q22, q00 + q11 + q22, 0.f);
    }
    __syncthreads();

    // ---- phase 2: pair scalar kernels (g, D1..D4)*nc and displacement ----
    const float A_ERF = 0.70710678118654752f;                         // 1/sqrt(2)
    const float NCE = (float)(90.4756 / (2.0 * 3.14159265358979323846));
    const float NCG = (float)((90.4756 / (2.0 * 3.14159265358979323846))
                              * 0.79788456080286536);                 // nc * 2a/sqrt(pi)

#pragma unroll
    for (int p = tid; p < NS * NT; p += TPB) {
        const int s  = p >> 4;
        const int tl = p & 15;
        float dx = s_tr[tl * 3 + 0] - s_sr[s * 3 + 0];
        float dy = s_tr[tl * 3 + 1] - s_sr[s * 3 + 1];
        float dz = s_tr[tl * 3 + 2] - s_sr[s * 3 + 2];
        float g = 0.f, c1 = 0.f, c2 = 0.f, c3 = 0.f, c4 = 0.f;
        if (t0 + tl != s0 + s) {
            float r2 = dx * dx + dy * dy + dz * dz;
            float rr = sqrtf(r2);
            float E  = NCE * erff(A_ERF * rr);
            float G  = NCG * expf(-0.5f * rr * rr);
            float ir = 1.0f / rr;
            float ir2 = ir * ir,  ir3 = ir2 * ir,  ir4 = ir2 * ir2, ir5 = ir4 * ir;
            float ir6 = ir4 * ir2, ir7 = ir6 * ir, ir8 = ir4 * ir4, ir9 = ir8 * ir;
            g  = E * ir;
            c1 = G * ir2 - E * ir3;
            c2 = 3.0f * E * ir5 - 3.0f * G * ir4 - G * ir2;                       // 2*a2 = 1
            c3 = -15.0f * E * ir7 + 15.0f * G * ir6 + 5.0f * G * ir4 + G * ir2;   // 10*a2=5, 4*a2^2=1
            c4 = 105.0f * E * ir9 - 105.0f * G * ir8 - 35.0f * G * ir6
                 - 7.0f * G * ir4 - G * ir2;                                      // 70a2=35, 28a2^2=7, 8a2^3=1
        }
        float4* op = (float4*)&s_pair[p * 8];
        op[0] = make_float4(g, c1, c2, c3);
        op[1] = make_float4(c4, dx, dy, dz);
    }
    __syncthreads();

    // ---- phase 3: per-(target, channel) accumulation over the source tile ----
    const int tl = tid >> 3;
    const int qc = tid & 7;

    float A0 = 0.f, A1 = 0.f, A2 = 0.f;
    float Eux = 0.f, Euy = 0.f, Euz = 0.f;
    float EQx = 0.f, EQy = 0.f, EQz = 0.f;
    float Efx = 0.f, Efy = 0.f, Efz = 0.f;
    float Qxx = 0.f, Qxy = 0.f, Qxz = 0.f, Qyy = 0.f, Qyz = 0.f, Qzz = 0.f;

#pragma unroll 8
    for (int s = 0; s < NS; s++) {
        const float4 pa = *(const float4*)&s_pair[(s * NT + tl) * 8];
        const float4 pb = *(const float4*)&s_pair[(s * NT + tl) * 8 + 4];
        const float g  = pa.x, c1 = pa.y, c2 = pa.z, c3 = pa.w;
        const float c4 = pb.x, dx = pb.y, dy = pb.z, dz = pb.w;
        const float4 f0 = *(const float4*)&s_src[(s * NQC + qc) * 12];
        const float4 f1 = *(const float4*)&s_src[(s * NQC + qc) * 12 + 4];
        const float4 f2 = *(const float4*)&s_src[(s * NQC + qc) * 12 + 8];
        const float qs = f0.x, ux = f0.y, uy = f0.z, uz = f0.w;
        const float S00 = f1.x, S01 = f1.y, S02 = f1.z, S11 = f1.w;
        const float S12 = f2.x, S22 = f2.y, trq = f2.z;

        const float ud  = fmaf(ux, dx, fmaf(uy, dy, uz * dz));
        // s = S·d  (== Q·d + Qᵀ·d);  dQd = ½ dᵀS d
        const float sx = fmaf(S00, dx, fmaf(S01, dy, S02 * dz));
        const float sy = fmaf(S01, dx, fmaf(S11, dy, S12 * dz));
        const float sz = fmaf(S02, dx, fmaf(S12, dy, S22 * dz));
        const float dQd = 0.5f * fmaf(dx, sx, fmaf(dy, sy, dz * sz));

        // potentials at target
        A0 = fmaf(g, qs, A0);
        A1 = fmaf(-c1, ud, A1);
        A2 = fmaf(0.5f * c2, dQd, A2);
        A2 = fmaf(0.5f * c1, trq, A2);

        // E_u (dipole field)
        const float t2u = c2 * ud;
        Eux = fmaf(t2u, dx, fmaf(c1, ux, Eux));
        Euy = fmaf(t2u, dy, fmaf(c1, uy, Euy));
        Euz = fmaf(t2u, dz, fmaf(c1, uz, Euz));

        // shared: cD = c3*dQd + c2*trq  (also = -2*Aq)
        const float cD = fmaf(c3, dQd, c2 * trq);

        // E_Q (quadrupole field):  Aq = -0.5*cD, Bq = -0.5*c2
        const float Aq = -0.5f * cD;
        const float Bq = -0.5f * c2;
        EQx = fmaf(Aq, dx, fmaf(Bq, sx, EQx));
        EQy = fmaf(Aq, dy, fmaf(Bq, sy, EQy));
        EQz = fmaf(Aq, dz, fmaf(Bq, sz, EQz));

        // field from charges
        const float t1q = c1 * qs;
        Efx = fmaf(-t1q, dx, Efx);
        Efy = fmaf(-t1q, dy, Efy);
        Efz = fmaf(-t1q, dz, Efz);

        // QQ (symmetric 3x3)
        const float cA = fmaf(c4, dQd, c3 * trq);
        const float hx = c3 * sx, hy = c3 * sy, hz = c3 * sz;
        Qxx = fmaf(cA, dx * dx, Qxx);
        Qxx = fmaf(hx + hx, dx, Qxx);
        Qxx = fmaf(c2, S00, Qxx + cD);
        Qyy = fmaf(cA, dy * dy, Qyy);
        Qyy = fmaf(hy + hy, dy, Qyy);
        Qyy = fmaf(c2, S11, Qyy + cD);
        Qzz = fmaf(cA, dz * dz, Qzz);
        Qzz = fmaf(hz + hz, dz, Qzz);
        Qzz = fmaf(c2, S22, Qzz + cD);
        Qxy = fmaf(cA, dx * dy, Qxy);
        Qxy = fmaf(hx, dy, Qxy);
        Qxy = fmaf(hy, dx, Qxy);
        Qxy = fmaf(c2, S01, Qxy);
        Qxz = fmaf(cA, dx * dz, Qxz);
        Qxz = fmaf(hx, dz, Qxz);
        Qxz = fmaf(hz, dx, Qxz);
        Qxz = fmaf(c2, S02, Qxz);
        Qyz = fmaf(cA, dy * dz, Qyz);
        Qyz = fmaf(hy, dz, Qyz);
        Qyz = fmaf(hz, dy, Qyz);
        Qyz = fmaf(c2, S12, Qyz);
    }

    // ---- accumulate partials into compact L2-resident array (red ops) ----
    const int tqi = (t0 + tl) * NQC + qc;
    const float acc[18] = {A0, A1, A2, Eux, Euy, Euz, EQx, EQy, EQz,
                           Efx, Efy, Efz, Qxx, Qxy, Qxz, Qyy, Qyz, Qzz};
#pragma unroll
    for (int k = 0; k < 18; k++)
        atomicAdd(&g_acc[k * NTQ + tqi], acc[k]);
}

// PDL secondary: starts while pairs drains, prefetches inputs that pairs does
// not write, then grid-syncs before touching g_acc / out.
__global__ __launch_bounds__(32)
void finalize_kernel(const float* __restrict__ gq, const float* __restrict__ gu,
                     const float* __restrict__ gQ, const float* __restrict__ gkap,
                     const float* __restrict__ gal, float* __restrict__ out)
{
    const int tqi = blockIdx.x * 32 + threadIdx.x;

    // prefetch inputs independent of pairs' outputs
    const float qv  = gq[tqi];
    const float kap = gkap[tqi];
    const float al  = gal[tqi];
    const float ux = gu[tqi * 3 + 0], uy = gu[tqi * 3 + 1], uz = gu[tqi * 3 + 2];
    float Qpv[9];
#pragma unroll
    for (int k = 0; k < 9; k++) Qpv[k] = gQ[tqi * 9 + k];

    // wait for pairs_kernel completion (all its atomics + out[0]=0 visible)
    cudaGridDependencySynchronize();

    float acc[18];
#pragma unroll
    for (int k = 0; k < 18; k++)
        acc[k] = g_acc[k * NTQ + tqi];
    // re-zero for the next invocation (self-cleaning accumulator)
#pragma unroll
    for (int k = 0; k < 18; k++)
        g_acc[k * NTQ + tqi] = 0.0f;

    const float A0 = acc[0], A1 = acc[1], A2 = acc[2];
    const float Eux = acc[3], Euy = acc[4], Euz = acc[5];
    const float EQx = acc[6], EQy = acc[7], EQz = acc[8];
    const float Efx = acc[9], Efy = acc[10], Efz = acc[11];
    const float Qxx = acc[12], Qxy = acc[13], Qxz = acc[14];
    const float Qyy = acc[15], Qyz = acc[16], Qzz = acc[17];

    const float ephi = A0 + A1 + A2;
    out[1 + tqi] = -kap * ephi;                               // q_induced

    const float ex = Efx + Eux + EQx;
    const float ey = Efy + Euy + EQy;
    const float ez = Efz + Euz + EQz;
    out[1 + NTQ + tqi * 3 + 0] = al * ex;                     // u_induced
    out[1 + NTQ + tqi * 3 + 1] = al * ey;
    out[1 + NTQ + tqi * 3 + 2] = al * ez;

    const float qQQ = Qpv[0] * Qxx + Qpv[4] * Qyy + Qpv[8] * Qzz
                    + (Qpv[1] + Qpv[3]) * Qxy + (Qpv[2] + Qpv[6]) * Qxz
                    + (Qpv[5] + Qpv[7]) * Qyz;
    const float uEu = ux * Eux + uy * Euy + uz * Euz;
    const float uEQ = ux * EQx + uy * EQy + uz * EQz;
    const float e2  = ex * ex + ey * ey + ez * ez;

    float pot = 0.5f * A0 * qv + A1 * qv - 0.5f * uEu + qv * A2
              + 0.125f * qQQ - uEQ
              - 0.5f * kap * ephi * ephi
              - 0.5f * al * e2;

    // warp-shuffle reduction, one atomic per block
#pragma unroll
    for (int off = 16; off > 0; off >>= 1)
        pot += __shfl_xor_sync(0xFFFFFFFFu, pot, off);
    if (threadIdx.x == 0) atomicAdd(&out[0], pot);
}

extern "C" void kernel_launch(void* const* d_in, const int* in_sizes, int n_in,
                              void* d_out, int out_size)
{
    (void)in_sizes; (void)n_in; (void)out_size;
    const float* q     = (const float*)d_in[0];
    const float* r     = (const float*)d_in[1];
    // d_in[2] = cell (zero -> realspace branch), d_in[3] = batch (single graph): unused
    const float* u     = (const float*)d_in[4];
    const float* quad  = (const float*)d_in[5];
    const float* kappa = (const float*)d_in[6];
    const float* alpha = (const float*)d_in[7];
    float* out = (float*)d_out;

    pairs_kernel<<<dim3(NTB, NCH), TPB>>>(q, r, u, quad, out);

    // finalize with Programmatic Dependent Launch: overlaps launch + input
    // prefetch with pairs' tail; cudaGridDependencySynchronize() inside the
    // kernel provides the ordering on g_acc / out.
    cudaLaunchConfig_t cfg = {};
    cfg.gridDim  = dim3(NTQ / 32, 1, 1);
    cfg.blockDim = dim3(32, 1, 1);
    cfg.dynamicSmemBytes = 0;
    cfg.stream = 0;
    cudaLaunchAttribute attrs[1];
    attrs[0].id = cudaLaunchAttributeProgrammaticStreamSerialization;
    attrs[0].val.programmaticStreamSerializationAllowed = 1;
    cfg.attrs = attrs;
    cfg.numAttrs = 1;
    cudaLaunchKernelEx(&cfg, finalize_kernel, q, u, quad, kappa, alpha, out);
}